// round 15
// baseline (speedup 1.0000x reference)
#include <cuda_runtime.h>
#include <cuda_bf16.h>
#include <mma.h>
#include <cstdint>

using namespace nvcuda;

// Problem constants
#define BATCH 2
#define SEQ   4096
#define DIM   256
#define PD    64          // proj_dim_l
#define RD    64          // proj_dim_r
#define ROWS  (BATCH*SEQ) // 8192

// ---------------------------------------------------------------------------
// Device scratch (no allocations allowed)
// ---------------------------------------------------------------------------
__device__ float g_v[(size_t)ROWS * DIM];   // x @ Wv
__device__ float g_l[(size_t)ROWS * PD];    // x @ Wl
__device__ float g_r[(size_t)ROWS * RD];    // x @ Wr
__device__ float g_M[ROWS];                 // row max of logits
__device__ float g_invZ[ROWS];              // 1 / softmax denominator
__device__ float g_o[(size_t)ROWS * DIM];   // score @ V

// ---------------------------------------------------------------------------
// FP32 SIMT GEMM: C[M,N] = A[M,K] @ W[K,N], all row-major fp32.
// Block tile 128x64, BK=32, 256 threads, thread micro-tile 8x4.
// Used for all projections (exact fp32 keeps logits / V / output precise).
// ---------------------------------------------------------------------------
__global__ void gemm_f32_kernel(const float* __restrict__ A,
                                const float* __restrict__ W,
                                float* __restrict__ C,
                                int M, int N, int K) {
    __shared__ float As[32][133];  // transposed [k][m], pad -> conflict-free
    __shared__ float Ws[32][68];   // [k][n]

    int tid = threadIdx.x;
    int tx  = tid & 15;            // 16 thread-cols * 4 = 64 N
    int ty  = tid >> 4;            // 16 thread-rows * 8 = 128 M
    int rowBase = blockIdx.x * 128;
    int colBase = blockIdx.y * 64;

    float acc[8][4];
#pragma unroll
    for (int i = 0; i < 8; i++)
#pragma unroll
        for (int j = 0; j < 4; j++) acc[i][j] = 0.0f;

    for (int kb = 0; kb < K; kb += 32) {
        // A tile 128x32 -> transposed store (4096 elems / 256 thr = 16)
#pragma unroll
        for (int j = 0; j < 16; j++) {
            int idx = tid + j * 256;
            int r = idx >> 5, c = idx & 31;
            As[c][r] = A[(size_t)(rowBase + r) * K + kb + c];
        }
        // W tile 32x64 (2048 / 256 = 8)
#pragma unroll
        for (int j = 0; j < 8; j++) {
            int idx = tid + j * 256;
            int r = idx >> 6, c = idx & 63;
            Ws[r][c] = W[(size_t)(kb + r) * N + colBase + c];
        }
        __syncthreads();

#pragma unroll
        for (int k = 0; k < 32; k++) {
            float a[8], b[4];
#pragma unroll
            for (int i = 0; i < 8; i++) a[i] = As[k][ty * 8 + i];
#pragma unroll
            for (int j = 0; j < 4; j++) b[j] = Ws[k][tx * 4 + j];
#pragma unroll
            for (int i = 0; i < 8; i++)
#pragma unroll
                for (int j = 0; j < 4; j++)
                    acc[i][j] = fmaf(a[i], b[j], acc[i][j]);
        }
        __syncthreads();
    }

#pragma unroll
    for (int i = 0; i < 8; i++) {
        float* crow = C + (size_t)(rowBase + ty * 8 + i) * N + colBase + tx * 4;
#pragma unroll
        for (int j = 0; j < 4; j++) crow[j] = acc[i][j];
    }
}

// ---------------------------------------------------------------------------
// Row max M and 1/Z for the factorized softmax.
// Row max over all (p,q) pairs of l_p*r_q = max of the 4 corner products.
// Z = sum_{p,q} exp(l_p*r_q - M). One block (128 thr) per row.
// ---------------------------------------------------------------------------
__global__ void mz_kernel() {
    int row = blockIdx.x;
    int tid = threadIdx.x;

    __shared__ float ls[64], rs[64];
    __shared__ float red[4];

    if (tid < 64) ls[tid] = g_l[(size_t)row * PD + tid];
    else          rs[tid - 64] = g_r[(size_t)row * RD + (tid - 64)];
    __syncthreads();

    float lmax = -1e30f, lmin = 1e30f, rmax = -1e30f, rmin = 1e30f;
#pragma unroll 8
    for (int i = 0; i < 64; i++) {
        float lv = ls[i], rv = rs[i];
        lmax = fmaxf(lmax, lv); lmin = fminf(lmin, lv);
        rmax = fmaxf(rmax, rv); rmin = fminf(rmin, rv);
    }
    float Mv = fmaxf(fmaxf(lmax * rmax, lmax * rmin),
                     fmaxf(lmin * rmax, lmin * rmin));

    float s = 0.0f;
    for (int idx = tid; idx < 4096; idx += 128) {
        int p = idx >> 6, q = idx & 63;
        s += __expf(fmaf(ls[p], rs[q], -Mv));
    }
#pragma unroll
    for (int off = 16; off; off >>= 1)
        s += __shfl_xor_sync(0xffffffffu, s, off);
    if ((tid & 31) == 0) red[tid >> 5] = s;
    __syncthreads();
    if (tid == 0) {
        float z = red[0] + red[1] + red[2] + red[3];
        g_M[row]    = Mv;
        g_invZ[row] = 1.0f / z;
    }
}

// ---------------------------------------------------------------------------
// Fused attention: O[n,:] = sum_m exp(l_p*r_q - M_n)*invZ_n * V[m,:]
// Block: 64 query rows x full D=256, 256 threads (8 warps, 2x4 warp grid,
// warp tile 32x64). K loop over p (64 iters, BK = 64 = one p-slab of V rows).
// Score tile recomputed on the fly (outer product + exp), P@V on tf32 wmma.
// V tiles double-buffered via cp.async (L2-resident: 4 MB per batch).
// ---------------------------------------------------------------------------
#define LDV 264
#define LDP 72
#define ATTN_SMEM_FLOATS (2*64*LDV + 64*LDP + 64*64 + 64*64 + 64 + 64)
#define ATTN_SMEM_BYTES  (ATTN_SMEM_FLOATS * 4)

__device__ __forceinline__ void cp_async16(uint32_t smem_dst, const void* gsrc) {
    asm volatile("cp.async.cg.shared.global [%0], [%1], 16;\n"
                 :: "r"(smem_dst), "l"(gsrc) : "memory");
}
__device__ __forceinline__ void cp_commit() {
    asm volatile("cp.async.commit_group;\n" ::: "memory");
}
template <int N>
__device__ __forceinline__ void cp_wait() {
    asm volatile("cp.async.wait_group %0;\n" :: "n"(N) : "memory");
}

__device__ __forceinline__ void load_v_tile(const float* __restrict__ Vb,
                                            int p, float* dst, int tid) {
    const float* src0 = Vb + (size_t)p * 64 * DIM;  // 64 rows x 256 cols
#pragma unroll
    for (int j = 0; j < 16; j++) {
        int idx = tid + j * 256;       // 0..4095 float4s
        int r   = idx >> 6;            // 0..63
        int c4  = idx & 63;            // 0..63 (x4 floats)
        uint32_t d = (uint32_t)__cvta_generic_to_shared(dst + r * LDV + c4 * 4);
        cp_async16(d, src0 + (size_t)r * DIM + c4 * 4);
    }
}

__global__ void attn_kernel() {
    extern __shared__ float sm[];
    float* sV  = sm;                    // 2 * 64 * LDV
    float* sP  = sV + 2 * 64 * LDV;     // 64 * LDP
    float* sL  = sP + 64 * LDP;         // 64 * 64
    float* sR  = sL + 64 * 64;          // 64 * 64
    float* sM  = sR + 64 * 64;          // 64
    float* sIZ = sM + 64;               // 64

    int tid  = threadIdx.x;
    int warp = tid >> 5;
    int wm   = warp >> 2;               // 0..1 : 32-row slab
    int wn   = warp & 3;                // 0..3 : 64-col slab
    int row0 = blockIdx.x * 64;
    int b    = row0 >> 12;              // /4096
    const float* Vb = g_v + (size_t)b * SEQ * DIM;

    // load l, r tiles (64x64 each) vectorized
#pragma unroll
    for (int j = 0; j < 4; j++) {
        int idx = tid + j * 256;        // 0..1023 float4s
        int r = idx >> 4, c4 = idx & 15;
        *reinterpret_cast<float4*>(&sL[r * 64 + c4 * 4]) =
            *reinterpret_cast<const float4*>(&g_l[(size_t)(row0 + r) * PD + c4 * 4]);
        *reinterpret_cast<float4*>(&sR[r * 64 + c4 * 4]) =
            *reinterpret_cast<const float4*>(&g_r[(size_t)(row0 + r) * RD + c4 * 4]);
    }
    if (tid < 64) { sM[tid] = g_M[row0 + tid]; sIZ[tid] = g_invZ[row0 + tid]; }

    // prefetch V tile 0
    load_v_tile(Vb, 0, sV, tid);
    cp_commit();
    __syncthreads();

    wmma::fragment<wmma::accumulator, 16, 16, 8, float> acc[2][4];
#pragma unroll
    for (int i = 0; i < 2; i++)
#pragma unroll
        for (int j = 0; j < 4; j++) wmma::fill_fragment(acc[i][j], 0.0f);

    // per-thread score-tile assignment: one row n, 16 q's
    int n  = tid >> 2;
    int q0 = (tid & 3) << 4;

    for (int p = 0; p < 64; ++p) {
        if (p + 1 < 64) {
            load_v_tile(Vb, p + 1, sV + ((p + 1) & 1) * 64 * LDV, tid);
            cp_commit();
        }

        // score tile: P[n][q] = exp(l[n][p]*r[n][q] - M[n]) * invZ[n]
        float lv = sL[n * 64 + p];
        float Mn = sM[n];
        float iz = sIZ[n];
#pragma unroll
        for (int j = 0; j < 16; j++) {
            float rv = sR[n * 64 + q0 + j];
            sP[n * LDP + q0 + j] = __expf(fmaf(lv, rv, -Mn)) * iz;
        }

        if (p + 1 < 64) cp_wait<1>(); else cp_wait<0>();
        __syncthreads();   // sP visible; sV[p&1] complete

        const float* Vt = sV + (p & 1) * 64 * LDV;

#pragma unroll
        for (int kk = 0; kk < 8; kk++) {
            wmma::fragment<wmma::matrix_a, 16, 16, 8, wmma::precision::tf32,
                           wmma::row_major> af[2];
#pragma unroll
            for (int i = 0; i < 2; i++) {
                wmma::load_matrix_sync(af[i], &sP[(wm * 32 + i * 16) * LDP + kk * 8], LDP);
#pragma unroll
                for (int t = 0; t < af[i].num_elements; t++)
                    af[i].x[t] = wmma::__float_to_tf32(af[i].x[t]);
            }
#pragma unroll
            for (int j = 0; j < 4; j++) {
                wmma::fragment<wmma::matrix_b, 16, 16, 8, wmma::precision::tf32,
                               wmma::row_major> bf;
                wmma::load_matrix_sync(bf, &Vt[(kk * 8) * LDV + wn * 64 + j * 16], LDV);
#pragma unroll
                for (int t = 0; t < bf.num_elements; t++)
                    bf.x[t] = wmma::__float_to_tf32(bf.x[t]);
                wmma::mma_sync(acc[0][j], af[0], bf, acc[0][j]);
                wmma::mma_sync(acc[1][j], af[1], bf, acc[1][j]);
            }
        }
        __syncthreads();   // all reads of sP / sV done before next iter rewrites
    }

    // scores already include 1/Z -> accumulators are final
#pragma unroll
    for (int i = 0; i < 2; i++)
#pragma unroll
        for (int j = 0; j < 4; j++)
            wmma::store_matrix_sync(
                &g_o[(size_t)(row0 + wm * 32 + i * 16) * DIM + wn * 64 + j * 16],
                acc[i][j], DIM, wmma::mem_row_major);
}

// ---------------------------------------------------------------------------
// kernel_launch
// Inputs (metadata order): x (2*4096*256), Wl (256*64), Wr (256*64),
//                          Wv (256*256), Wo (256*256).  Output fp32 (2,4096,256).
// ---------------------------------------------------------------------------
extern "C" void kernel_launch(void* const* d_in, const int* in_sizes, int n_in,
                              void* d_out, int out_size) {
    const float* x  = (const float*)d_in[0];
    const float* Wl = (const float*)d_in[1];
    const float* Wr = (const float*)d_in[2];
    const float* Wv = (const float*)d_in[3];
    const float* Wo = (const float*)d_in[4];
    float* out = (float*)d_out;

    (void)in_sizes; (void)n_in; (void)out_size;

    // resolve device-global scratch addresses (pure lookup, capture-safe)
    float *pv = nullptr, *pl = nullptr, *pr = nullptr, *po = nullptr;
    cudaGetSymbolAddress((void**)&pv, g_v);
    cudaGetSymbolAddress((void**)&pl, g_l);
    cudaGetSymbolAddress((void**)&pr, g_r);
    cudaGetSymbolAddress((void**)&po, g_o);

    cudaFuncSetAttribute(attn_kernel,
                         cudaFuncAttributeMaxDynamicSharedMemorySize,
                         ATTN_SMEM_BYTES);

    // projections (exact fp32)
    gemm_f32_kernel<<<dim3(ROWS / 128, DIM / 64), 256>>>(x, Wv, pv, ROWS, DIM, DIM);
    gemm_f32_kernel<<<dim3(ROWS / 128, 1),        256>>>(x, Wl, pl, ROWS, PD,  DIM);
    gemm_f32_kernel<<<dim3(ROWS / 128, 1),        256>>>(x, Wr, pr, ROWS, RD,  DIM);

    // softmax statistics
    mz_kernel<<<ROWS, 128>>>();

    // fused factorized attention (tf32 tensor cores)
    attn_kernel<<<ROWS / 64, 256, ATTN_SMEM_BYTES>>>();

    // output projection (exact fp32)
    gemm_f32_kernel<<<dim3(ROWS / 128, DIM / 64), 256>>>(po, Wo, out, ROWS, DIM, DIM);
}

// round 16
// speedup vs baseline: 1.0010x; 1.0010x over previous
#include <cuda_runtime.h>
#include <cuda_bf16.h>
#include <mma.h>
#include <cstdint>

using namespace nvcuda;

// Problem constants
#define BATCH 2
#define SEQ   4096
#define DIM   256
#define PD    64          // proj_dim_l
#define RD    64          // proj_dim_r
#define ROWS  (BATCH*SEQ) // 8192

// ---------------------------------------------------------------------------
// Device scratch (no allocations allowed)
// ---------------------------------------------------------------------------
__device__ float g_v[(size_t)ROWS * DIM];   // x @ Wv
__device__ float g_l[(size_t)ROWS * PD];    // x @ Wl
__device__ float g_r[(size_t)ROWS * RD];    // x @ Wr
__device__ float g_M[ROWS];                 // row max of logits
__device__ float g_invZ[ROWS];              // 1 / softmax denominator
__device__ float g_o[(size_t)ROWS * DIM];   // score @ V

// ---------------------------------------------------------------------------
// FP32 SIMT GEMM: C[M,N] = A[M,K] @ W[K,N], all row-major fp32.
// Block tile 128x64, BK=32, 256 threads, thread micro-tile 8x4.
// Used for all projections (exact fp32 keeps logits / V / output precise).
// ---------------------------------------------------------------------------
__global__ void gemm_f32_kernel(const float* __restrict__ A,
                                const float* __restrict__ W,
                                float* __restrict__ C,
                                int M, int N, int K) {
    __shared__ float As[32][133];  // transposed [k][m], pad -> conflict-free
    __shared__ float Ws[32][68];   // [k][n]

    int tid = threadIdx.x;
    int tx  = tid & 15;            // 16 thread-cols * 4 = 64 N
    int ty  = tid >> 4;            // 16 thread-rows * 8 = 128 M
    int rowBase = blockIdx.x * 128;
    int colBase = blockIdx.y * 64;

    float acc[8][4];
#pragma unroll
    for (int i = 0; i < 8; i++)
#pragma unroll
        for (int j = 0; j < 4; j++) acc[i][j] = 0.0f;

    for (int kb = 0; kb < K; kb += 32) {
        // A tile 128x32 -> transposed store (4096 elems / 256 thr = 16)
#pragma unroll
        for (int j = 0; j < 16; j++) {
            int idx = tid + j * 256;
            int r = idx >> 5, c = idx & 31;
            As[c][r] = A[(size_t)(rowBase + r) * K + kb + c];
        }
        // W tile 32x64 (2048 / 256 = 8)
#pragma unroll
        for (int j = 0; j < 8; j++) {
            int idx = tid + j * 256;
            int r = idx >> 6, c = idx & 63;
            Ws[r][c] = W[(size_t)(kb + r) * N + colBase + c];
        }
        __syncthreads();

#pragma unroll
        for (int k = 0; k < 32; k++) {
            float a[8], b[4];
#pragma unroll
            for (int i = 0; i < 8; i++) a[i] = As[k][ty * 8 + i];
#pragma unroll
            for (int j = 0; j < 4; j++) b[j] = Ws[k][tx * 4 + j];
#pragma unroll
            for (int i = 0; i < 8; i++)
#pragma unroll
                for (int j = 0; j < 4; j++)
                    acc[i][j] = fmaf(a[i], b[j], acc[i][j]);
        }
        __syncthreads();
    }

#pragma unroll
    for (int i = 0; i < 8; i++) {
        float* crow = C + (size_t)(rowBase + ty * 8 + i) * N + colBase + tx * 4;
#pragma unroll
        for (int j = 0; j < 4; j++) crow[j] = acc[i][j];
    }
}

// ---------------------------------------------------------------------------
// Row max M and 1/Z for the factorized softmax.
// Row max over all (p,q) pairs of l_p*r_q = max of the 4 corner products.
// Z = sum_{p,q} exp(l_p*r_q - M). One block (128 thr) per row.
// ---------------------------------------------------------------------------
__global__ void mz_kernel() {
    int row = blockIdx.x;
    int tid = threadIdx.x;

    __shared__ float ls[64], rs[64];
    __shared__ float red[4];

    if (tid < 64) ls[tid] = g_l[(size_t)row * PD + tid];
    else          rs[tid - 64] = g_r[(size_t)row * RD + (tid - 64)];
    __syncthreads();

    float lmax = -1e30f, lmin = 1e30f, rmax = -1e30f, rmin = 1e30f;
#pragma unroll 8
    for (int i = 0; i < 64; i++) {
        float lv = ls[i], rv = rs[i];
        lmax = fmaxf(lmax, lv); lmin = fminf(lmin, lv);
        rmax = fmaxf(rmax, rv); rmin = fminf(rmin, rv);
    }
    float Mv = fmaxf(fmaxf(lmax * rmax, lmax * rmin),
                     fmaxf(lmin * rmax, lmin * rmin));

    float s = 0.0f;
    for (int idx = tid; idx < 4096; idx += 128) {
        int p = idx >> 6, q = idx & 63;
        s += __expf(fmaf(ls[p], rs[q], -Mv));
    }
#pragma unroll
    for (int off = 16; off; off >>= 1)
        s += __shfl_xor_sync(0xffffffffu, s, off);
    if ((tid & 31) == 0) red[tid >> 5] = s;
    __syncthreads();
    if (tid == 0) {
        float z = red[0] + red[1] + red[2] + red[3];
        g_M[row]    = Mv;
        g_invZ[row] = 1.0f / z;
    }
}

// ---------------------------------------------------------------------------
// Fused attention: O[n,:] = sum_m exp(l_p*r_q - M_n)*invZ_n * V[m,:]
// Block: 64 query rows x full D=256, 256 threads (8 warps, 2x4 warp grid,
// warp tile 32x64). K loop over p (64 iters, BK = 64 = one p-slab of V rows).
// Score tile recomputed on the fly (outer product + exp), P@V on tf32 wmma.
// V tiles double-buffered via cp.async (L2-resident: 4 MB per batch).
// ---------------------------------------------------------------------------
#define LDV 264
#define LDP 72
#define ATTN_SMEM_FLOATS (2*64*LDV + 64*LDP + 64*64 + 64*64 + 64 + 64)
#define ATTN_SMEM_BYTES  (ATTN_SMEM_FLOATS * 4)

__device__ __forceinline__ void cp_async16(uint32_t smem_dst, const void* gsrc) {
    asm volatile("cp.async.cg.shared.global [%0], [%1], 16;\n"
                 :: "r"(smem_dst), "l"(gsrc) : "memory");
}
__device__ __forceinline__ void cp_commit() {
    asm volatile("cp.async.commit_group;\n" ::: "memory");
}
template <int N>
__device__ __forceinline__ void cp_wait() {
    asm volatile("cp.async.wait_group %0;\n" :: "n"(N) : "memory");
}

__device__ __forceinline__ void load_v_tile(const float* __restrict__ Vb,
                                            int p, float* dst, int tid) {
    const float* src0 = Vb + (size_t)p * 64 * DIM;  // 64 rows x 256 cols
#pragma unroll
    for (int j = 0; j < 16; j++) {
        int idx = tid + j * 256;       // 0..4095 float4s
        int r   = idx >> 6;            // 0..63
        int c4  = idx & 63;            // 0..63 (x4 floats)
        uint32_t d = (uint32_t)__cvta_generic_to_shared(dst + r * LDV + c4 * 4);
        cp_async16(d, src0 + (size_t)r * DIM + c4 * 4);
    }
}

__global__ void attn_kernel() {
    extern __shared__ float sm[];
    float* sV  = sm;                    // 2 * 64 * LDV
    float* sP  = sV + 2 * 64 * LDV;     // 64 * LDP
    float* sL  = sP + 64 * LDP;         // 64 * 64
    float* sR  = sL + 64 * 64;          // 64 * 64
    float* sM  = sR + 64 * 64;          // 64
    float* sIZ = sM + 64;               // 64

    int tid  = threadIdx.x;
    int warp = tid >> 5;
    int wm   = warp >> 2;               // 0..1 : 32-row slab
    int wn   = warp & 3;                // 0..3 : 64-col slab
    int row0 = blockIdx.x * 64;
    int b    = row0 >> 12;              // /4096
    const float* Vb = g_v + (size_t)b * SEQ * DIM;

    // load l, r tiles (64x64 each) vectorized
#pragma unroll
    for (int j = 0; j < 4; j++) {
        int idx = tid + j * 256;        // 0..1023 float4s
        int r = idx >> 4, c4 = idx & 15;
        *reinterpret_cast<float4*>(&sL[r * 64 + c4 * 4]) =
            *reinterpret_cast<const float4*>(&g_l[(size_t)(row0 + r) * PD + c4 * 4]);
        *reinterpret_cast<float4*>(&sR[r * 64 + c4 * 4]) =
            *reinterpret_cast<const float4*>(&g_r[(size_t)(row0 + r) * RD + c4 * 4]);
    }
    if (tid < 64) { sM[tid] = g_M[row0 + tid]; sIZ[tid] = g_invZ[row0 + tid]; }

    // prefetch V tile 0
    load_v_tile(Vb, 0, sV, tid);
    cp_commit();
    __syncthreads();

    wmma::fragment<wmma::accumulator, 16, 16, 8, float> acc[2][4];
#pragma unroll
    for (int i = 0; i < 2; i++)
#pragma unroll
        for (int j = 0; j < 4; j++) wmma::fill_fragment(acc[i][j], 0.0f);

    // per-thread score-tile assignment: one row n, 16 q's
    int n  = tid >> 2;
    int q0 = (tid & 3) << 4;

    for (int p = 0; p < 64; ++p) {
        if (p + 1 < 64) {
            load_v_tile(Vb, p + 1, sV + ((p + 1) & 1) * 64 * LDV, tid);
            cp_commit();
        }

        // score tile: P[n][q] = exp(l[n][p]*r[n][q] - M[n]) * invZ[n]
        float lv = sL[n * 64 + p];
        float Mn = sM[n];
        float iz = sIZ[n];
#pragma unroll
        for (int j = 0; j < 16; j++) {
            float rv = sR[n * 64 + q0 + j];
            sP[n * LDP + q0 + j] = __expf(fmaf(lv, rv, -Mn)) * iz;
        }

        if (p + 1 < 64) cp_wait<1>(); else cp_wait<0>();
        __syncthreads();   // sP visible; sV[p&1] complete

        const float* Vt = sV + (p & 1) * 64 * LDV;

#pragma unroll
        for (int kk = 0; kk < 8; kk++) {
            wmma::fragment<wmma::matrix_a, 16, 16, 8, wmma::precision::tf32,
                           wmma::row_major> af[2];
#pragma unroll
            for (int i = 0; i < 2; i++) {
                wmma::load_matrix_sync(af[i], &sP[(wm * 32 + i * 16) * LDP + kk * 8], LDP);
#pragma unroll
                for (int t = 0; t < af[i].num_elements; t++)
                    af[i].x[t] = wmma::__float_to_tf32(af[i].x[t]);
            }
#pragma unroll
            for (int j = 0; j < 4; j++) {
                wmma::fragment<wmma::matrix_b, 16, 16, 8, wmma::precision::tf32,
                               wmma::row_major> bf;
                wmma::load_matrix_sync(bf, &Vt[(kk * 8) * LDV + wn * 64 + j * 16], LDV);
#pragma unroll
                for (int t = 0; t < bf.num_elements; t++)
                    bf.x[t] = wmma::__float_to_tf32(bf.x[t]);
                wmma::mma_sync(acc[0][j], af[0], bf, acc[0][j]);
                wmma::mma_sync(acc[1][j], af[1], bf, acc[1][j]);
            }
        }
        __syncthreads();   // all reads of sP / sV done before next iter rewrites
    }

    // scores already include 1/Z -> accumulators are final
#pragma unroll
    for (int i = 0; i < 2; i++)
#pragma unroll
        for (int j = 0; j < 4; j++)
            wmma::store_matrix_sync(
                &g_o[(size_t)(row0 + wm * 32 + i * 16) * DIM + wn * 64 + j * 16],
                acc[i][j], DIM, wmma::mem_row_major);
}

// ---------------------------------------------------------------------------
// kernel_launch
// Inputs (metadata order): x (2*4096*256), Wl (256*64), Wr (256*64),
//                          Wv (256*256), Wo (256*256).  Output fp32 (2,4096,256).
// ---------------------------------------------------------------------------
extern "C" void kernel_launch(void* const* d_in, const int* in_sizes, int n_in,
                              void* d_out, int out_size) {
    const float* x  = (const float*)d_in[0];
    const float* Wl = (const float*)d_in[1];
    const float* Wr = (const float*)d_in[2];
    const float* Wv = (const float*)d_in[3];
    const float* Wo = (const float*)d_in[4];
    float* out = (float*)d_out;

    (void)in_sizes; (void)n_in; (void)out_size;

    // resolve device-global scratch addresses (pure lookup, capture-safe)
    float *pv = nullptr, *pl = nullptr, *pr = nullptr, *po = nullptr;
    cudaGetSymbolAddress((void**)&pv, g_v);
    cudaGetSymbolAddress((void**)&pl, g_l);
    cudaGetSymbolAddress((void**)&pr, g_r);
    cudaGetSymbolAddress((void**)&po, g_o);

    cudaFuncSetAttribute(attn_kernel,
                         cudaFuncAttributeMaxDynamicSharedMemorySize,
                         ATTN_SMEM_BYTES);

    // projections (exact fp32)
    gemm_f32_kernel<<<dim3(ROWS / 128, DIM / 64), 256>>>(x, Wv, pv, ROWS, DIM, DIM);
    gemm_f32_kernel<<<dim3(ROWS / 128, 1),        256>>>(x, Wl, pl, ROWS, PD,  DIM);
    gemm_f32_kernel<<<dim3(ROWS / 128, 1),        256>>>(x, Wr, pr, ROWS, RD,  DIM);

    // softmax statistics
    mz_kernel<<<ROWS, 128>>>();

    // fused factorized attention (tf32 tensor cores)
    attn_kernel<<<ROWS / 64, 256, ATTN_SMEM_BYTES>>>();

    // output projection (exact fp32)
    gemm_f32_kernel<<<dim3(ROWS / 128, DIM / 64), 256>>>(po, Wo, out, ROWS, DIM, DIM);
}

// round 17
// speedup vs baseline: 1.0018x; 1.0008x over previous
#include <cuda_runtime.h>
#include <cuda_bf16.h>
#include <mma.h>
#include <cstdint>

using namespace nvcuda;

// Problem constants
#define BATCH 2
#define SEQ   4096
#define DIM   256
#define PD    64          // proj_dim_l
#define RD    64          // proj_dim_r
#define ROWS  (BATCH*SEQ) // 8192

// ---------------------------------------------------------------------------
// Device scratch (no allocations allowed)
// ---------------------------------------------------------------------------
__device__ float g_v[(size_t)ROWS * DIM];   // x @ Wv
__device__ float g_l[(size_t)ROWS * PD];    // x @ Wl
__device__ float g_r[(size_t)ROWS * RD];    // x @ Wr
__device__ float g_M[ROWS];                 // row max of logits
__device__ float g_invZ[ROWS];              // 1 / softmax denominator
__device__ float g_o[(size_t)ROWS * DIM];   // score @ V

// ---------------------------------------------------------------------------
// FP32 SIMT GEMM: C[M,N] = A[M,K] @ W[K,N], all row-major fp32.
// Block tile 128x64, BK=32, 256 threads, thread micro-tile 8x4.
// Used for all projections (exact fp32 keeps logits / V / output precise).
// ---------------------------------------------------------------------------
__global__ void gemm_f32_kernel(const float* __restrict__ A,
                                const float* __restrict__ W,
                                float* __restrict__ C,
                                int M, int N, int K) {
    __shared__ float As[32][133];  // transposed [k][m], pad -> conflict-free
    __shared__ float Ws[32][68];   // [k][n]

    int tid = threadIdx.x;
    int tx  = tid & 15;            // 16 thread-cols * 4 = 64 N
    int ty  = tid >> 4;            // 16 thread-rows * 8 = 128 M
    int rowBase = blockIdx.x * 128;
    int colBase = blockIdx.y * 64;

    float acc[8][4];
#pragma unroll
    for (int i = 0; i < 8; i++)
#pragma unroll
        for (int j = 0; j < 4; j++) acc[i][j] = 0.0f;

    for (int kb = 0; kb < K; kb += 32) {
        // A tile 128x32 -> transposed store (4096 elems / 256 thr = 16)
#pragma unroll
        for (int j = 0; j < 16; j++) {
            int idx = tid + j * 256;
            int r = idx >> 5, c = idx & 31;
            As[c][r] = A[(size_t)(rowBase + r) * K + kb + c];
        }
        // W tile 32x64 (2048 / 256 = 8)
#pragma unroll
        for (int j = 0; j < 8; j++) {
            int idx = tid + j * 256;
            int r = idx >> 6, c = idx & 63;
            Ws[r][c] = W[(size_t)(kb + r) * N + colBase + c];
        }
        __syncthreads();

#pragma unroll
        for (int k = 0; k < 32; k++) {
            float a[8], b[4];
#pragma unroll
            for (int i = 0; i < 8; i++) a[i] = As[k][ty * 8 + i];
#pragma unroll
            for (int j = 0; j < 4; j++) b[j] = Ws[k][tx * 4 + j];
#pragma unroll
            for (int i = 0; i < 8; i++)
#pragma unroll
                for (int j = 0; j < 4; j++)
                    acc[i][j] = fmaf(a[i], b[j], acc[i][j]);
        }
        __syncthreads();
    }

#pragma unroll
    for (int i = 0; i < 8; i++) {
        float* crow = C + (size_t)(rowBase + ty * 8 + i) * N + colBase + tx * 4;
#pragma unroll
        for (int j = 0; j < 4; j++) crow[j] = acc[i][j];
    }
}

// ---------------------------------------------------------------------------
// Row max M and 1/Z for the factorized softmax.
// Row max over all (p,q) pairs of l_p*r_q = max of the 4 corner products.
// Z = sum_{p,q} exp(l_p*r_q - M). One block (128 thr) per row.
// ---------------------------------------------------------------------------
__global__ void mz_kernel() {
    int row = blockIdx.x;
    int tid = threadIdx.x;

    __shared__ float ls[64], rs[64];
    __shared__ float red[4];

    if (tid < 64) ls[tid] = g_l[(size_t)row * PD + tid];
    else          rs[tid - 64] = g_r[(size_t)row * RD + (tid - 64)];
    __syncthreads();

    float lmax = -1e30f, lmin = 1e30f, rmax = -1e30f, rmin = 1e30f;
#pragma unroll 8
    for (int i = 0; i < 64; i++) {
        float lv = ls[i], rv = rs[i];
        lmax = fmaxf(lmax, lv); lmin = fminf(lmin, lv);
        rmax = fmaxf(rmax, rv); rmin = fminf(rmin, rv);
    }
    float Mv = fmaxf(fmaxf(lmax * rmax, lmax * rmin),
                     fmaxf(lmin * rmax, lmin * rmin));

    float s = 0.0f;
    for (int idx = tid; idx < 4096; idx += 128) {
        int p = idx >> 6, q = idx & 63;
        s += __expf(fmaf(ls[p], rs[q], -Mv));
    }
#pragma unroll
    for (int off = 16; off; off >>= 1)
        s += __shfl_xor_sync(0xffffffffu, s, off);
    if ((tid & 31) == 0) red[tid >> 5] = s;
    __syncthreads();
    if (tid == 0) {
        float z = red[0] + red[1] + red[2] + red[3];
        g_M[row]    = Mv;
        g_invZ[row] = 1.0f / z;
    }
}

// ---------------------------------------------------------------------------
// Fused attention: O[n,:] = sum_m exp(l_p*r_q - M_n)*invZ_n * V[m,:]
// Block: 64 query rows x full D=256, 256 threads (8 warps, 2x4 warp grid,
// warp tile 32x64). K loop over p (64 iters, BK = 64 = one p-slab of V rows).
// Score tile recomputed on the fly (outer product + exp), P@V on tf32 wmma.
// V tiles double-buffered via cp.async (L2-resident: 4 MB per batch).
// ---------------------------------------------------------------------------
#define LDV 264
#define LDP 72
#define ATTN_SMEM_FLOATS (2*64*LDV + 64*LDP + 64*64 + 64*64 + 64 + 64)
#define ATTN_SMEM_BYTES  (ATTN_SMEM_FLOATS * 4)

__device__ __forceinline__ void cp_async16(uint32_t smem_dst, const void* gsrc) {
    asm volatile("cp.async.cg.shared.global [%0], [%1], 16;\n"
                 :: "r"(smem_dst), "l"(gsrc) : "memory");
}
__device__ __forceinline__ void cp_commit() {
    asm volatile("cp.async.commit_group;\n" ::: "memory");
}
template <int N>
__device__ __forceinline__ void cp_wait() {
    asm volatile("cp.async.wait_group %0;\n" :: "n"(N) : "memory");
}

__device__ __forceinline__ void load_v_tile(const float* __restrict__ Vb,
                                            int p, float* dst, int tid) {
    const float* src0 = Vb + (size_t)p * 64 * DIM;  // 64 rows x 256 cols
#pragma unroll
    for (int j = 0; j < 16; j++) {
        int idx = tid + j * 256;       // 0..4095 float4s
        int r   = idx >> 6;            // 0..63
        int c4  = idx & 63;            // 0..63 (x4 floats)
        uint32_t d = (uint32_t)__cvta_generic_to_shared(dst + r * LDV + c4 * 4);
        cp_async16(d, src0 + (size_t)r * DIM + c4 * 4);
    }
}

__global__ void attn_kernel() {
    extern __shared__ float sm[];
    float* sV  = sm;                    // 2 * 64 * LDV
    float* sP  = sV + 2 * 64 * LDV;     // 64 * LDP
    float* sL  = sP + 64 * LDP;         // 64 * 64
    float* sR  = sL + 64 * 64;          // 64 * 64
    float* sM  = sR + 64 * 64;          // 64
    float* sIZ = sM + 64;               // 64

    int tid  = threadIdx.x;
    int warp = tid >> 5;
    int wm   = warp >> 2;               // 0..1 : 32-row slab
    int wn   = warp & 3;                // 0..3 : 64-col slab
    int row0 = blockIdx.x * 64;
    int b    = row0 >> 12;              // /4096
    const float* Vb = g_v + (size_t)b * SEQ * DIM;

    // load l, r tiles (64x64 each) vectorized
#pragma unroll
    for (int j = 0; j < 4; j++) {
        int idx = tid + j * 256;        // 0..1023 float4s
        int r = idx >> 4, c4 = idx & 15;
        *reinterpret_cast<float4*>(&sL[r * 64 + c4 * 4]) =
            *reinterpret_cast<const float4*>(&g_l[(size_t)(row0 + r) * PD + c4 * 4]);
        *reinterpret_cast<float4*>(&sR[r * 64 + c4 * 4]) =
            *reinterpret_cast<const float4*>(&g_r[(size_t)(row0 + r) * RD + c4 * 4]);
    }
    if (tid < 64) { sM[tid] = g_M[row0 + tid]; sIZ[tid] = g_invZ[row0 + tid]; }

    // prefetch V tile 0
    load_v_tile(Vb, 0, sV, tid);
    cp_commit();
    __syncthreads();

    wmma::fragment<wmma::accumulator, 16, 16, 8, float> acc[2][4];
#pragma unroll
    for (int i = 0; i < 2; i++)
#pragma unroll
        for (int j = 0; j < 4; j++) wmma::fill_fragment(acc[i][j], 0.0f);

    // per-thread score-tile assignment: one row n, 16 q's
    int n  = tid >> 2;
    int q0 = (tid & 3) << 4;

    for (int p = 0; p < 64; ++p) {
        if (p + 1 < 64) {
            load_v_tile(Vb, p + 1, sV + ((p + 1) & 1) * 64 * LDV, tid);
            cp_commit();
        }

        // score tile: P[n][q] = exp(l[n][p]*r[n][q] - M[n]) * invZ[n]
        float lv = sL[n * 64 + p];
        float Mn = sM[n];
        float iz = sIZ[n];
#pragma unroll
        for (int j = 0; j < 16; j++) {
            float rv = sR[n * 64 + q0 + j];
            sP[n * LDP + q0 + j] = __expf(fmaf(lv, rv, -Mn)) * iz;
        }

        if (p + 1 < 64) cp_wait<1>(); else cp_wait<0>();
        __syncthreads();   // sP visible; sV[p&1] complete

        const float* Vt = sV + (p & 1) * 64 * LDV;

#pragma unroll
        for (int kk = 0; kk < 8; kk++) {
            wmma::fragment<wmma::matrix_a, 16, 16, 8, wmma::precision::tf32,
                           wmma::row_major> af[2];
#pragma unroll
            for (int i = 0; i < 2; i++) {
                wmma::load_matrix_sync(af[i], &sP[(wm * 32 + i * 16) * LDP + kk * 8], LDP);
#pragma unroll
                for (int t = 0; t < af[i].num_elements; t++)
                    af[i].x[t] = wmma::__float_to_tf32(af[i].x[t]);
            }
#pragma unroll
            for (int j = 0; j < 4; j++) {
                wmma::fragment<wmma::matrix_b, 16, 16, 8, wmma::precision::tf32,
                               wmma::row_major> bf;
                wmma::load_matrix_sync(bf, &Vt[(kk * 8) * LDV + wn * 64 + j * 16], LDV);
#pragma unroll
                for (int t = 0; t < bf.num_elements; t++)
                    bf.x[t] = wmma::__float_to_tf32(bf.x[t]);
                wmma::mma_sync(acc[0][j], af[0], bf, acc[0][j]);
                wmma::mma_sync(acc[1][j], af[1], bf, acc[1][j]);
            }
        }
        __syncthreads();   // all reads of sP / sV done before next iter rewrites
    }

    // scores already include 1/Z -> accumulators are final
#pragma unroll
    for (int i = 0; i < 2; i++)
#pragma unroll
        for (int j = 0; j < 4; j++)
            wmma::store_matrix_sync(
                &g_o[(size_t)(row0 + wm * 32 + i * 16) * DIM + wn * 64 + j * 16],
                acc[i][j], DIM, wmma::mem_row_major);
}

// ---------------------------------------------------------------------------
// kernel_launch
// Inputs (metadata order): x (2*4096*256), Wl (256*64), Wr (256*64),
//                          Wv (256*256), Wo (256*256).  Output fp32 (2,4096,256).
// ---------------------------------------------------------------------------
extern "C" void kernel_launch(void* const* d_in, const int* in_sizes, int n_in,
                              void* d_out, int out_size) {
    const float* x  = (const float*)d_in[0];
    const float* Wl = (const float*)d_in[1];
    const float* Wr = (const float*)d_in[2];
    const float* Wv = (const float*)d_in[3];
    const float* Wo = (const float*)d_in[4];
    float* out = (float*)d_out;

    (void)in_sizes; (void)n_in; (void)out_size;

    // resolve device-global scratch addresses (pure lookup, capture-safe)
    float *pv = nullptr, *pl = nullptr, *pr = nullptr, *po = nullptr;
    cudaGetSymbolAddress((void**)&pv, g_v);
    cudaGetSymbolAddress((void**)&pl, g_l);
    cudaGetSymbolAddress((void**)&pr, g_r);
    cudaGetSymbolAddress((void**)&po, g_o);

    cudaFuncSetAttribute(attn_kernel,
                         cudaFuncAttributeMaxDynamicSharedMemorySize,
                         ATTN_SMEM_BYTES);

    // projections (exact fp32)
    gemm_f32_kernel<<<dim3(ROWS / 128, DIM / 64), 256>>>(x, Wv, pv, ROWS, DIM, DIM);
    gemm_f32_kernel<<<dim3(ROWS / 128, 1),        256>>>(x, Wl, pl, ROWS, PD,  DIM);
    gemm_f32_kernel<<<dim3(ROWS / 128, 1),        256>>>(x, Wr, pr, ROWS, RD,  DIM);

    // softmax statistics
    mz_kernel<<<ROWS, 128>>>();

    // fused factorized attention (tf32 tensor cores)
    attn_kernel<<<ROWS / 64, 256, ATTN_SMEM_BYTES>>>();

    // output projection (exact fp32)
    gemm_f32_kernel<<<dim3(ROWS / 128, DIM / 64), 256>>>(po, Wo, out, ROWS, DIM, DIM);
}